// round 10
// baseline (speedup 1.0000x reference)
#include <cuda_runtime.h>
#include <cuda_bf16.h>
#include <cstdint>

#define NHEAD 8
#define HD 128
#define BSZ 1024
#define CDIM 1024
#define NB 32
#define THREADS 512
#define SCALE 0.08838834764831845f   // HD^-0.5

#define XPITCH 136    // bf16 elems per x row (272B = 17*16B: ldmatrix conflict-free)
#define WROWB 272     // bytes per W row (16 chunks data + 1 pad)
#define QP 130        // bf16 elems per qkv row (260B: odd word pitch, conflict-free)

// ---- smem byte offsets ----
#define SM_XHI   0                    // 32*136*2 = 8704
#define SM_WB    8704                 // 2 stage buffers * WBUF_SZ
#define WBUF_SZ  34816                // 128 rows * 272 B
#define SM_QKV   78336                // bf16[3][32][QP] = 3*8320 = 24960
#define SM_TOTAL 103296
// epilogue overlays (x + W buf0 dead after last ldmatrix)
#define SM_RED   8704                 // float[16][32][13] = 26624
#define SM_COEF  35328                // float[32][13] = 1664

__device__ __nv_bfloat16 g_whi[NHEAD * 3 * HD * HD];
__device__ float g_wvsum[NHEAD * HD];   // per-head column sums of Wv

__device__ __forceinline__ float rcpf(float x) {
    float y; asm("rcp.approx.ftz.f32 %0, %1;" : "=f"(y) : "f"(x)); return y;
}
__device__ __forceinline__ uint32_t smem_u32(const void* p) {
    uint32_t a;
    asm("{ .reg .u64 t; cvta.to.shared.u64 t, %1; cvt.u32.u64 %0, t; }" : "=r"(a) : "l"(p));
    return a;
}
__device__ __forceinline__ void cp_async16(uint32_t dst, const void* src) {
    asm volatile("cp.async.ca.shared.global [%0], [%1], 16;" :: "r"(dst), "l"(src) : "memory");
}
#define CP_COMMIT() asm volatile("cp.async.commit_group;" ::: "memory")
#define CP_WAIT0()  asm volatile("cp.async.wait_group 0;" ::: "memory")

__device__ __forceinline__ void ldm_x4(uint32_t& r0, uint32_t& r1, uint32_t& r2, uint32_t& r3,
                                       uint32_t addr) {
    asm volatile("ldmatrix.sync.aligned.m8n8.x4.shared.b16 {%0,%1,%2,%3}, [%4];"
                 : "=r"(r0), "=r"(r1), "=r"(r2), "=r"(r3) : "r"(addr));
}
__device__ __forceinline__ void mma_bf16(float c[4],
    uint32_t a0, uint32_t a1, uint32_t a2, uint32_t a3,
    uint32_t b0, uint32_t b1)
{
    asm volatile(
        "mma.sync.aligned.m16n8k16.row.col.f32.bf16.bf16.f32 "
        "{%0,%1,%2,%3}, {%4,%5,%6,%7}, {%8,%9}, {%0,%1,%2,%3};"
        : "+f"(c[0]), "+f"(c[1]), "+f"(c[2]), "+f"(c[3])
        : "r"(a0), "r"(a1), "r"(a2), "r"(a3), "r"(b0), "r"(b1));
}
__device__ __forceinline__ uint32_t bits2(__nv_bfloat162 v) {
    return *reinterpret_cast<uint32_t*>(&v);
}

// ================= prestage: fp32 W -> bf16 (+ Wv column sums) =================
__global__ __launch_bounds__(256) void conv_kernel(
    const float* __restrict__ Wq, const float* __restrict__ Wkv)
{
    if (blockIdx.x >= 384) {
        __shared__ float ps[2][128];
        const int h = blockIdx.x - 384;
        const int tid = threadIdx.x;
        const int d = tid & 127, part = tid >> 7;
        const float* src = Wkv + (size_t)h * 32768 + 16384 + d + (size_t)part * 64 * 128;
        float s = 0.f;
        #pragma unroll 16
        for (int e = 0; e < 64; ++e) s += src[(size_t)e * 128];
        ps[part][d] = s;
        __syncthreads();
        if (part == 0) g_wvsum[h * 128 + d] = ps[0][d] + ps[1][d];
        return;
    }
    int i4  = blockIdx.x * 256 + threadIdx.x;
    int idx = i4 * 4;
    int hm  = idx >> 14;
    int h   = hm / 3, m = hm % 3;
    int nk  = idx & 16383;
    const float* src;
    float scl = 1.0f;
    if (m == 0)      src = Wq  + (size_t)h * 16384 + nk;
    else if (m == 1) { src = Wkv + (size_t)h * 32768 + nk; scl = SCALE; }
    else             src = Wkv + (size_t)h * 32768 + 16384 + nk;

    float4 f = *(const float4*)src;
    f.x *= scl; f.y *= scl; f.z *= scl; f.w *= scl;
    __nv_bfloat162 h01 = __floats2bfloat162_rn(f.x, f.y);
    __nv_bfloat162 h23 = __floats2bfloat162_rn(f.z, f.w);
    *(uint2*)(g_whi + idx) = make_uint2(bits2(h01), bits2(h23));
}

// ================= main kernel =================
__global__ __launch_bounds__(THREADS) void satt_kernel(
    const float* __restrict__ x,
    float* __restrict__ out)
{
    extern __shared__ char smem[];
    const uint32_t sbase = smem_u32(smem);
    const int tid  = threadIdx.x;
    const int wid  = tid >> 5, lane = tid & 31;
    const int g    = lane >> 2, tg = lane & 3;
    const int h    = blockIdx.y;
    const int b0   = blockIdx.x * NB;

    // ---- issue cp.async for W stage 0 ----
    {
        const __nv_bfloat16* wsrc = g_whi + (size_t)(h * 3 + 0) * 16384;
        #pragma unroll
        for (int j = 0; j < 4; ++j) {
            int c = tid + j * 512;               // 0..2047
            int r = c >> 4, ch = c & 15;
            cp_async16(sbase + SM_WB + r * WROWB + ch * 16,
                       wsrc + (size_t)r * 128 + ch * 8);
        }
        CP_COMMIT();
    }

    // ---- stage x (bf16 hi only) ----
    #pragma unroll
    for (int j = 0; j < 2; ++j) {
        int i4 = tid + j * 512;                  // float4 idx over 32x128
        int b  = i4 >> 5, dq = (i4 & 31) * 4;
        float4 f = *(const float4*)(x + (size_t)(b0 + b) * CDIM + h * HD + dq);
        __nv_bfloat162 h01 = __floats2bfloat162_rn(f.x, f.y);
        __nv_bfloat162 h23 = __floats2bfloat162_rn(f.z, f.w);
        uint32_t* ph = (uint32_t*)(smem + SM_XHI + (size_t)(b * XPITCH + dq) * 2);
        ph[0] = bits2(h01); ph[1] = bits2(h23);
    }

    const int mg = wid >> 3;              // 0/1: 16-batch half
    const int n0 = (wid & 7) * 16;        // 16 output cols per warp

    // ---- per-lane ldmatrix offsets ----
    const int a_row = (lane & 7) + ((lane & 8) ? 8 : 0);
    const int a_kof = (lane & 16) ? 8 : 0;
    const int b_n   = n0 + (lane & 7) + ((lane & 16) ? 8 : 0);
    const uint32_t b_lane_off = (uint32_t)b_n * WROWB + ((lane & 8) ? 16 : 0);

    float acc[2][4];

    // ---- 3 pipelined stages (q, k, v), double-buffered W ----
    for (int s = 0; s < 3; ++s) {
        CP_WAIT0();
        __syncthreads();

        if (s < 2) {
            const __nv_bfloat16* wsrc = g_whi + (size_t)(h * 3 + s + 1) * 16384;
            const uint32_t dbuf = sbase + SM_WB + ((s + 1) & 1) * WBUF_SZ;
            #pragma unroll
            for (int j = 0; j < 4; ++j) {
                int c = tid + j * 512;
                int r = c >> 4, ch = c & 15;
                cp_async16(dbuf + r * WROWB + ch * 16, wsrc + (size_t)r * 128 + ch * 8);
            }
            CP_COMMIT();
        }

        #pragma unroll
        for (int b = 0; b < 2; ++b)
            #pragma unroll
            for (int c = 0; c < 4; ++c) acc[b][c] = 0.f;

        const uint32_t buf = sbase + SM_WB + (s & 1) * WBUF_SZ;

        #pragma unroll
        for (int ktl = 0; ktl < 8; ++ktl) {
            const int k0 = ktl * 16;
            uint32_t A[4];
            {
                const uint32_t aoff =
                    (uint32_t)((mg * 16 + a_row) * XPITCH + k0 + a_kof) * 2;
                ldm_x4(A[0], A[1], A[2], A[3], sbase + SM_XHI + aoff);
            }
            uint32_t Bf[2][2];
            ldm_x4(Bf[0][0], Bf[0][1], Bf[1][0], Bf[1][1],
                   buf + b_lane_off + (uint32_t)k0 * 2);
            #pragma unroll
            for (int Nt = 0; Nt < 2; ++Nt)
                mma_bf16(acc[Nt], A[0], A[1], A[2], A[3], Bf[Nt][0], Bf[Nt][1]);
        }

        {   // write q/k/v tile as bf16 (pack pairs)
            char* dst = smem + SM_QKV + (size_t)s * NB * QP * 2;
            const int r = mg * 16 + g;
            #pragma unroll
            for (int Nt = 0; Nt < 2; ++Nt) {
                int c = n0 + Nt * 8 + 2 * tg;
                *(uint32_t*)(dst + (size_t)r * QP * 2 + c * 2) =
                    bits2(__floats2bfloat162_rn(acc[Nt][0], acc[Nt][1]));
                *(uint32_t*)(dst + (size_t)(r + 8) * QP * 2 + c * 2) =
                    bits2(__floats2bfloat162_rn(acc[Nt][2], acc[Nt][3]));
            }
        }
    }
    __syncthreads();

    // ================= epilogue: separable moment softmax =================
    const char* q_s = smem + SM_QKV;
    const char* k_s = q_s + NB * QP * 2;
    const char* v_s = q_s + 2 * NB * QP * 2;
    float* red  = (float*)(smem + SM_RED);
    float* coef = (float*)(smem + SM_COEF);

    {   // Phase A: moments over 8 e's + exact fp32 S0 partial over 8 d's
        const int b = tid & 31, part = tid >> 5;   // 16 parts
        float K1=0,K2=0,K3=0,K4=0,K5=0,K6=0;
        float S1=0,S2=0,S3=0,S4=0,S5=0,S6=0;
        #pragma unroll
        for (int i = 0; i < 8; ++i) {
            int e = part * 8 + i;
            float kv = __bfloat162float(*(const __nv_bfloat16*)(k_s + (size_t)b * QP * 2 + e * 2));
            float vv = __bfloat162float(*(const __nv_bfloat16*)(v_s + (size_t)b * QP * 2 + e * 2));
            float t = kv; K1 += t; S1 = fmaf(t, vv, S1);
            t *= kv;      K2 += t; S2 = fmaf(t, vv, S2);
            t *= kv;      K3 += t; S3 = fmaf(t, vv, S3);
            t *= kv;      K4 += t; S4 = fmaf(t, vv, S4);
            t *= kv;      K5 += t; S5 = fmaf(t, vv, S5);
            t *= kv;      K6 += t; S6 = fmaf(t, vv, S6);
        }
        float S0 = 0.f;
        {
            const float* xb = x + (size_t)(b0 + b) * CDIM + h * HD + part * 8;
            const float* wv = g_wvsum + h * 128 + part * 8;
            #pragma unroll
            for (int i = 0; i < 8; ++i)
                S0 = fmaf(__ldg(&xb[i]), __ldg(&wv[i]), S0);
        }
        float* rr = red + ((size_t)part * 32 + b) * 13;
        rr[0]=K1; rr[1]=K2; rr[2]=K3; rr[3]=K4; rr[4]=K5; rr[5]=K6;
        rr[6]=S0; rr[7]=S1; rr[8]=S2; rr[9]=S3; rr[10]=S4; rr[11]=S5; rr[12]=S6;
    }
    __syncthreads();

    if (tid < 32) {   // Phase B: combine 16 parts + fold 1/n!
        float c[13];
        #pragma unroll
        for (int j = 0; j < 13; ++j) c[j] = 0.f;
        #pragma unroll
        for (int p = 0; p < 16; ++p) {
            const float* rr = red + ((size_t)p * 32 + tid) * 13;
            #pragma unroll
            for (int j = 0; j < 13; ++j) c[j] += rr[j];
        }
        float* cc = coef + tid * 13;
        cc[0] = c[0];               cc[1] = c[1] * 0.5f;
        cc[2] = c[2] * (1.f/6.f);   cc[3] = c[3] * (1.f/24.f);
        cc[4] = c[4] * (1.f/120.f); cc[5] = c[5] * (1.f/720.f);
        cc[6] = c[6];               cc[7] = c[7];
        cc[8] = c[8] * 0.5f;        cc[9] = c[9] * (1.f/6.f);
        cc[10]= c[10]* (1.f/24.f);  cc[11]= c[11]* (1.f/120.f);
        cc[12]= c[12]* (1.f/720.f);
    }
    __syncthreads();

    {   // Phase C: Horner, write gmem directly
        const int b = tid & 31, part = tid >> 5;
        const float* cc = coef + b * 13;
        const float a1=cc[0],a2=cc[1],a3=cc[2],a4=cc[3],a5=cc[4],a6=cc[5];
        const float g0=cc[6],g1=cc[7],g2=cc[8],g3=cc[9],g4=cc[10],g5=cc[11],g6=cc[12];
        float o[8];
        #pragma unroll
        for (int i = 0; i < 8; ++i) {
            int d = part * 8 + i;
            float q = __bfloat162float(*(const __nv_bfloat16*)(q_s + (size_t)b * QP * 2 + d * 2));
            float den = fmaf(a6, q, a5);
            den = fmaf(den, q, a4); den = fmaf(den, q, a3);
            den = fmaf(den, q, a2); den = fmaf(den, q, a1);
            den = fmaf(den, q, 128.0f);
            float num = fmaf(g6, q, g5);
            num = fmaf(num, q, g4); num = fmaf(num, q, g3);
            num = fmaf(num, q, g2); num = fmaf(num, q, g1);
            num = fmaf(num, q, g0);
            o[i] = num * rcpf(den);
        }
        float* dst = out + (size_t)(b0 + b) * CDIM + h * HD + part * 8;
        *(float4*)(dst)     = make_float4(o[0], o[1], o[2], o[3]);
        *(float4*)(dst + 4) = make_float4(o[4], o[5], o[6], o[7]);
    }
}

extern "C" void kernel_launch(void* const* d_in, const int* in_sizes, int n_in,
                              void* d_out, int out_size) {
    const float* x   = (const float*)d_in[0];
    const float* Wq  = (const float*)d_in[1];
    const float* Wkv = (const float*)d_in[2];
    float* out = (float*)d_out;

    conv_kernel<<<392, 256>>>(Wq, Wkv);

    cudaFuncSetAttribute(satt_kernel, cudaFuncAttributeMaxDynamicSharedMemorySize, SM_TOTAL);
    dim3 grid(BSZ / NB, NHEAD);
    satt_kernel<<<grid, THREADS, SM_TOTAL>>>(x, out);
}

// round 14
// speedup vs baseline: 1.4247x; 1.4247x over previous
#include <cuda_runtime.h>
#include <cuda_bf16.h>
#include <cstdint>

#define NHEAD 8
#define HD 128
#define BSZ 1024
#define CDIM 1024
#define NB 64
#define THREADS 512
#define SCALE 0.08838834764831845f   // HD^-0.5

#define XPITCH 136    // bf16 elems per x row (272B = 17*16B: ldmatrix conflict-free)
#define WROWB 272     // bytes per W row (272 = 17*16: conflict-free)
#define QPITCH 129    // f32 elems per row

// ---- smem byte offsets ----
#define SM_X     0                    // 64*136*2 = 17408
#define SM_WB    17408                // 3 buffers * WBUF_SZ
#define WBUF_SZ  34816                // 128 rows * 272 B
#define SM_QKV   121856               // float[3][64][QPITCH] = 99072
#define SM_TOTAL 220928
// epilogue overlays (x + W regions dead after mainloop)
#define SM_RED   0                    // float[8][64][13] = 26624
#define SM_COEF  28672                // float[64][13] = 3328

__device__ __nv_bfloat16 g_whi[NHEAD * 3 * HD * HD];
__device__ float g_wvsum[NHEAD * HD];   // per-head column sums of Wv

__device__ __forceinline__ float rcpf(float x) {
    float y; asm("rcp.approx.ftz.f32 %0, %1;" : "=f"(y) : "f"(x)); return y;
}
__device__ __forceinline__ uint32_t smem_u32(const void* p) {
    uint32_t a;
    asm("{ .reg .u64 t; cvta.to.shared.u64 t, %1; cvt.u32.u64 %0, t; }" : "=r"(a) : "l"(p));
    return a;
}
__device__ __forceinline__ void cp_async16(uint32_t dst, const void* src) {
    asm volatile("cp.async.ca.shared.global [%0], [%1], 16;" :: "r"(dst), "l"(src) : "memory");
}
#define CP_COMMIT() asm volatile("cp.async.commit_group;" ::: "memory")
#define CP_WAIT0()  asm volatile("cp.async.wait_group 0;" ::: "memory")

__device__ __forceinline__ void ldm_x4(uint32_t& r0, uint32_t& r1, uint32_t& r2, uint32_t& r3,
                                       uint32_t addr) {
    asm volatile("ldmatrix.sync.aligned.m8n8.x4.shared.b16 {%0,%1,%2,%3}, [%4];"
                 : "=r"(r0), "=r"(r1), "=r"(r2), "=r"(r3) : "r"(addr));
}
__device__ __forceinline__ void mma_bf16(float c[4],
    uint32_t a0, uint32_t a1, uint32_t a2, uint32_t a3,
    uint32_t b0, uint32_t b1)
{
    asm volatile(
        "mma.sync.aligned.m16n8k16.row.col.f32.bf16.bf16.f32 "
        "{%0,%1,%2,%3}, {%4,%5,%6,%7}, {%8,%9}, {%0,%1,%2,%3};"
        : "+f"(c[0]), "+f"(c[1]), "+f"(c[2]), "+f"(c[3])
        : "r"(a0), "r"(a1), "r"(a2), "r"(a3), "r"(b0), "r"(b1));
}
__device__ __forceinline__ uint32_t bits2(__nv_bfloat162 v) {
    return *reinterpret_cast<uint32_t*>(&v);
}

// ================= prestage: fp32 W -> bf16 (+ Wv column sums) =================
__global__ __launch_bounds__(256) void conv_kernel(
    const float* __restrict__ Wq, const float* __restrict__ Wkv)
{
    if (blockIdx.x >= 384) {
        __shared__ float ps[2][128];
        const int h = blockIdx.x - 384;
        const int tid = threadIdx.x;
        const int d = tid & 127, part = tid >> 7;
        const float* src = Wkv + (size_t)h * 32768 + 16384 + d + (size_t)part * 64 * 128;
        float s = 0.f;
        #pragma unroll 16
        for (int e = 0; e < 64; ++e) s += src[(size_t)e * 128];
        ps[part][d] = s;
        __syncthreads();
        if (part == 0) g_wvsum[h * 128 + d] = ps[0][d] + ps[1][d];
        return;
    }
    int i4  = blockIdx.x * 256 + threadIdx.x;
    int idx = i4 * 4;
    int hm  = idx >> 14;
    int h   = hm / 3, m = hm % 3;
    int nk  = idx & 16383;
    const float* src;
    float scl = 1.0f;
    if (m == 0)      src = Wq  + (size_t)h * 16384 + nk;
    else if (m == 1) { src = Wkv + (size_t)h * 32768 + nk; scl = SCALE; }
    else             src = Wkv + (size_t)h * 32768 + 16384 + nk;

    float4 f = *(const float4*)src;
    f.x *= scl; f.y *= scl; f.z *= scl; f.w *= scl;
    __nv_bfloat162 h01 = __floats2bfloat162_rn(f.x, f.y);
    __nv_bfloat162 h23 = __floats2bfloat162_rn(f.z, f.w);
    *(uint2*)(g_whi + idx) = make_uint2(bits2(h01), bits2(h23));
}

// ================= main kernel =================
__global__ __launch_bounds__(THREADS, 1) void satt_kernel(
    const float* __restrict__ x,
    float* __restrict__ out)
{
    extern __shared__ char smem[];
    const uint32_t sbase = smem_u32(smem);
    const int tid  = threadIdx.x;
    const int wid  = tid >> 5, lane = tid & 31;
    const int g    = lane >> 2, tg = lane & 3;
    const int h    = blockIdx.y;
    const int b0   = blockIdx.x * NB;

    // ---- issue cp.async for ALL THREE W matrices (96 KB) ----
    {
        const __nv_bfloat16* wsrc = g_whi + (size_t)h * 3 * 16384;
        #pragma unroll
        for (int j = 0; j < 12; ++j) {
            int c = tid + j * 512;               // 0..6143 chunks of 16B
            int mm = c >> 11;                    // matrix
            int r  = (c >> 4) & 127, ch = c & 15;
            cp_async16(sbase + SM_WB + mm * WBUF_SZ + r * WROWB + ch * 16,
                       wsrc + (size_t)mm * 16384 + (size_t)r * 128 + ch * 8);
        }
        CP_COMMIT();
    }

    // ---- stage x (bf16) ----
    #pragma unroll
    for (int j = 0; j < 4; ++j) {
        int i4 = tid + j * 512;                  // float4 idx over 64x128
        int b  = i4 >> 5, dq = (i4 & 31) * 4;
        float4 f = *(const float4*)(x + (size_t)(b0 + b) * CDIM + h * HD + dq);
        __nv_bfloat162 h01 = __floats2bfloat162_rn(f.x, f.y);
        __nv_bfloat162 h23 = __floats2bfloat162_rn(f.z, f.w);
        uint32_t* ph = (uint32_t*)(smem + SM_X + (size_t)(b * XPITCH + dq) * 2);
        ph[0] = bits2(h01); ph[1] = bits2(h23);
    }

    const int mg = wid >> 3;              // 0/1: 32-batch half
    const int n0 = (wid & 7) * 16;        // 16 output cols per warp

    // ---- per-lane ldmatrix offsets ----
    const int a_row = (lane & 7) + ((lane & 8) ? 8 : 0);
    const int a_kof = (lane & 16) ? 8 : 0;
    const int b_n   = n0 + (lane & 7) + ((lane & 16) ? 8 : 0);
    const uint32_t b_lane_off = (uint32_t)b_n * WROWB + ((lane & 8) ? 16 : 0);

    CP_WAIT0();
    __syncthreads();

    // ---- fused mma region: ktl outer (A loaded once), matrices inner ----
    float acc[3][2][2][4];   // [matrix][Mt][Nt][frag]
    #pragma unroll
    for (int m = 0; m < 3; ++m)
        #pragma unroll
        for (int a = 0; a < 2; ++a)
            #pragma unroll
            for (int b = 0; b < 2; ++b)
                #pragma unroll
                for (int c = 0; c < 4; ++c) acc[m][a][b][c] = 0.f;

    #pragma unroll
    for (int ktl = 0; ktl < 8; ++ktl) {
        const int k0 = ktl * 16;
        uint32_t A[2][4];   // [Mt][frag]
        #pragma unroll
        for (int Mt = 0; Mt < 2; ++Mt) {
            const uint32_t aoff =
                (uint32_t)((mg * 32 + Mt * 16 + a_row) * XPITCH + k0 + a_kof) * 2;
            ldm_x4(A[Mt][0], A[Mt][1], A[Mt][2], A[Mt][3], sbase + SM_X + aoff);
        }
        #pragma unroll
        for (int m = 0; m < 3; ++m) {
            uint32_t Bf[2][2];
            ldm_x4(Bf[0][0], Bf[0][1], Bf[1][0], Bf[1][1],
                   sbase + SM_WB + m * WBUF_SZ + b_lane_off + (uint32_t)k0 * 2);
            #pragma unroll
            for (int Mt = 0; Mt < 2; ++Mt)
                #pragma unroll
                for (int Nt = 0; Nt < 2; ++Nt)
                    mma_bf16(acc[m][Mt][Nt], A[Mt][0], A[Mt][1], A[Mt][2], A[Mt][3],
                             Bf[Nt][0], Bf[Nt][1]);
        }
    }

    // ---- write q/k/v tiles (fp32) ----
    #pragma unroll
    for (int m = 0; m < 3; ++m) {
        float* dst = (float*)(smem + SM_QKV) + (size_t)m * NB * QPITCH;
        #pragma unroll
        for (int Mt = 0; Mt < 2; ++Mt) {
            const int r = mg * 32 + Mt * 16 + g;
            #pragma unroll
            for (int Nt = 0; Nt < 2; ++Nt) {
                int c = n0 + Nt * 8 + 2 * tg;
                dst[r * QPITCH + c]            = acc[m][Mt][Nt][0];
                dst[r * QPITCH + c + 1]        = acc[m][Mt][Nt][1];
                dst[(r + 8) * QPITCH + c]      = acc[m][Mt][Nt][2];
                dst[(r + 8) * QPITCH + c + 1]  = acc[m][Mt][Nt][3];
            }
        }
    }
    __syncthreads();

    // ================= epilogue: separable moment softmax =================
    const float* q_s = (const float*)(smem + SM_QKV);
    const float* k_s = q_s + NB * QPITCH;
    const float* v_s = q_s + 2 * NB * QPITCH;
    float* red  = (float*)(smem + SM_RED);
    float* coef = (float*)(smem + SM_COEF);

    {   // Phase A: moments over 16 e's + exact fp32 S0 partial over 16 d's
        const int b = tid & 63, part = tid >> 6;   // 8 parts
        float K1=0,K2=0,K3=0,K4=0,K5=0,K6=0;
        float S1=0,S2=0,S3=0,S4=0,S5=0,S6=0;
        #pragma unroll
        for (int i = 0; i < 16; ++i) {
            int e = part * 16 + i;
            float kv = k_s[b * QPITCH + e];   // = k * SCALE (folded in conv)
            float vv = v_s[b * QPITCH + e];
            float t = kv; K1 += t; S1 = fmaf(t, vv, S1);
            t *= kv;      K2 += t; S2 = fmaf(t, vv, S2);
            t *= kv;      K3 += t; S3 = fmaf(t, vv, S3);
            t *= kv;      K4 += t; S4 = fmaf(t, vv, S4);
            t *= kv;      K5 += t; S5 = fmaf(t, vv, S5);
            t *= kv;      K6 += t; S6 = fmaf(t, vv, S6);
        }
        float S0 = 0.f;
        {
            const float* xb = x + (size_t)(b0 + b) * CDIM + h * HD + part * 16;
            const float* wv = g_wvsum + h * 128 + part * 16;
            #pragma unroll
            for (int i = 0; i < 16; ++i)
                S0 = fmaf(__ldg(&xb[i]), __ldg(&wv[i]), S0);
        }
        float* rr = red + ((size_t)part * 64 + b) * 13;
        rr[0]=K1; rr[1]=K2; rr[2]=K3; rr[3]=K4; rr[4]=K5; rr[5]=K6;
        rr[6]=S0; rr[7]=S1; rr[8]=S2; rr[9]=S3; rr[10]=S4; rr[11]=S5; rr[12]=S6;
    }
    __syncthreads();

    if (tid < 64) {   // Phase B: combine 8 parts + fold 1/n!
        float c[13];
        #pragma unroll
        for (int j = 0; j < 13; ++j) c[j] = 0.f;
        #pragma unroll
        for (int p = 0; p < 8; ++p) {
            const float* rr = red + ((size_t)p * 64 + tid) * 13;
            #pragma unroll
            for (int j = 0; j < 13; ++j) c[j] += rr[j];
        }
        float* cc = coef + tid * 13;
        cc[0] = c[0];               cc[1] = c[1] * 0.5f;
        cc[2] = c[2] * (1.f/6.f);   cc[3] = c[3] * (1.f/24.f);
        cc[4] = c[4] * (1.f/120.f); cc[5] = c[5] * (1.f/720.f);
        cc[6] = c[6];               cc[7] = c[7];
        cc[8] = c[8] * 0.5f;        cc[9] = c[9] * (1.f/6.f);
        cc[10]= c[10]* (1.f/24.f);  cc[11]= c[11]* (1.f/120.f);
        cc[12]= c[12]* (1.f/720.f);
    }
    __syncthreads();

    {   // Phase C: Horner, write gmem directly (16 contiguous floats / thread)
        const int b = tid & 63, part = tid >> 6;
        const float* cc = coef + b * 13;
        const float a1=cc[0],a2=cc[1],a3=cc[2],a4=cc[3],a5=cc[4],a6=cc[5];
        const float g0=cc[6],g1=cc[7],g2=cc[8],g3=cc[9],g4=cc[10],g5=cc[11],g6=cc[12];
        float o[16];
        #pragma unroll
        for (int i = 0; i < 16; ++i) {
            int d = part * 16 + i;
            float q = q_s[b * QPITCH + d];
            float den = fmaf(a6, q, a5);
            den = fmaf(den, q, a4); den = fmaf(den, q, a3);
            den = fmaf(den, q, a2); den = fmaf(den, q, a1);
            den = fmaf(den, q, 128.0f);
            float num = fmaf(g6, q, g5);
            num = fmaf(num, q, g4); num = fmaf(num, q, g3);
            num = fmaf(num, q, g2); num = fmaf(num, q, g1);
            num = fmaf(num, q, g0);
            o[i] = num * rcpf(den);
        }
        float* dst = out + (size_t)(b0 + b) * CDIM + h * HD + part * 16;
        #pragma unroll
        for (int j = 0; j < 4; ++j)
            *(float4*)(dst + j * 4) = make_float4(o[j*4], o[j*4+1], o[j*4+2], o[j*4+3]);
    }
}

extern "C" void kernel_launch(void* const* d_in, const int* in_sizes, int n_in,
                              void* d_out, int out_size) {
    const float* x   = (const float*)d_in[0];
    const float* Wq  = (const float*)d_in[1];
    const float* Wkv = (const float*)d_in[2];
    float* out = (float*)d_out;

    conv_kernel<<<392, 256>>>(Wq, Wkv);

    cudaFuncSetAttribute(satt_kernel, cudaFuncAttributeMaxDynamicSharedMemorySize, SM_TOTAL);
    dim3 grid(BSZ / NB, NHEAD);
    satt_kernel<<<grid, THREADS, SM_TOTAL>>>(x, out);
}

// round 15
// speedup vs baseline: 1.7682x; 1.2411x over previous
#include <cuda_runtime.h>
#include <cuda_bf16.h>
#include <cstdint>

#define NHEAD 8
#define HD 128
#define BSZ 1024
#define CDIM 1024
#define NB 64
#define THREADS 512
#define SCALE 0.08838834764831845f   // HD^-0.5

#define XPITCH 136    // bf16 elems per x row (272B = 17*16B: ldmatrix conflict-free)
#define WROWB 272     // bytes per W row (272 = 17*16: conflict-free)
#define QPITCH 130    // f32 elems per qkv row (even: float2-aligned)

// ---- smem byte offsets ----
#define SM_X     0                    // 64*136*2 = 17408
#define SM_WB    17408                // 3 buffers * WBUF_SZ
#define WBUF_SZ  34816                // 128 rows * 272 B -> end 121856
#define SM_QKV   121856               // float[3][64][QPITCH] = 99840 -> end 221696
#define SM_S0    221696               // float[8][64] = 2048
#define SM_TOTAL 223744
// epilogue overlays (x + W regions dead after mainloop)
#define SM_RED   0                    // float[8][64][10] = 20480
#define SM_COEF  20480                // float[64][10] = 2560

__device__ __nv_bfloat16 g_whi[NHEAD * 3 * HD * HD];
__device__ float g_wvsum[NHEAD * HD];   // per-head column sums of Wv

__device__ __forceinline__ float rcpf(float x) {
    float y; asm("rcp.approx.ftz.f32 %0, %1;" : "=f"(y) : "f"(x)); return y;
}
__device__ __forceinline__ uint32_t smem_u32(const void* p) {
    uint32_t a;
    asm("{ .reg .u64 t; cvta.to.shared.u64 t, %1; cvt.u32.u64 %0, t; }" : "=r"(a) : "l"(p));
    return a;
}
__device__ __forceinline__ void cp_async16(uint32_t dst, const void* src) {
    asm volatile("cp.async.ca.shared.global [%0], [%1], 16;" :: "r"(dst), "l"(src) : "memory");
}
#define CP_COMMIT() asm volatile("cp.async.commit_group;" ::: "memory")
#define CP_WAIT0()  asm volatile("cp.async.wait_group 0;" ::: "memory")

__device__ __forceinline__ void ldm_x4(uint32_t& r0, uint32_t& r1, uint32_t& r2, uint32_t& r3,
                                       uint32_t addr) {
    asm volatile("ldmatrix.sync.aligned.m8n8.x4.shared.b16 {%0,%1,%2,%3}, [%4];"
                 : "=r"(r0), "=r"(r1), "=r"(r2), "=r"(r3) : "r"(addr));
}
__device__ __forceinline__ void mma_bf16(float c[4],
    uint32_t a0, uint32_t a1, uint32_t a2, uint32_t a3,
    uint32_t b0, uint32_t b1)
{
    asm volatile(
        "mma.sync.aligned.m16n8k16.row.col.f32.bf16.bf16.f32 "
        "{%0,%1,%2,%3}, {%4,%5,%6,%7}, {%8,%9}, {%0,%1,%2,%3};"
        : "+f"(c[0]), "+f"(c[1]), "+f"(c[2]), "+f"(c[3])
        : "r"(a0), "r"(a1), "r"(a2), "r"(a3), "r"(b0), "r"(b1));
}
__device__ __forceinline__ uint32_t bits2(__nv_bfloat162 v) {
    return *reinterpret_cast<uint32_t*>(&v);
}

// ================= prestage: fp32 W -> bf16 (+ Wv column sums) =================
__global__ __launch_bounds__(256) void conv_kernel(
    const float* __restrict__ Wq, const float* __restrict__ Wkv)
{
    if (blockIdx.x >= 384) {
        __shared__ float ps[2][128];
        const int h = blockIdx.x - 384;
        const int tid = threadIdx.x;
        const int d = tid & 127, part = tid >> 7;
        const float* src = Wkv + (size_t)h * 32768 + 16384 + d + (size_t)part * 64 * 128;
        float s = 0.f;
        #pragma unroll 16
        for (int e = 0; e < 64; ++e) s += src[(size_t)e * 128];
        ps[part][d] = s;
        __syncthreads();
        if (part == 0) g_wvsum[h * 128 + d] = ps[0][d] + ps[1][d];
        return;
    }
    int i4  = blockIdx.x * 256 + threadIdx.x;
    int idx = i4 * 4;
    int hm  = idx >> 14;
    int h   = hm / 3, m = hm % 3;
    int nk  = idx & 16383;
    const float* src;
    float scl = 1.0f;
    if (m == 0)      src = Wq  + (size_t)h * 16384 + nk;
    else if (m == 1) { src = Wkv + (size_t)h * 32768 + nk; scl = SCALE; }
    else             src = Wkv + (size_t)h * 32768 + 16384 + nk;

    float4 f = *(const float4*)src;
    f.x *= scl; f.y *= scl; f.z *= scl; f.w *= scl;
    __nv_bfloat162 h01 = __floats2bfloat162_rn(f.x, f.y);
    __nv_bfloat162 h23 = __floats2bfloat162_rn(f.z, f.w);
    *(uint2*)(g_whi + idx) = make_uint2(bits2(h01), bits2(h23));
}

// ================= main kernel =================
__global__ __launch_bounds__(THREADS, 1) void satt_kernel(
    const float* __restrict__ x,
    float* __restrict__ out)
{
    extern __shared__ char smem[];
    const uint32_t sbase = smem_u32(smem);
    const int tid  = threadIdx.x;
    const int wid  = tid >> 5, lane = tid & 31;
    const int g    = lane >> 2, tg = lane & 3;
    const int h    = blockIdx.y;
    const int b0   = blockIdx.x * NB;

    // ---- issue cp.async for ALL THREE W matrices (96 KB) ----
    {
        const __nv_bfloat16* wsrc = g_whi + (size_t)h * 3 * 16384;
        #pragma unroll
        for (int j = 0; j < 12; ++j) {
            int c = tid + j * 512;               // 0..6143 chunks of 16B
            int mm = c >> 11;                    // matrix
            int r  = (c >> 4) & 127, ch = c & 15;
            cp_async16(sbase + SM_WB + mm * WBUF_SZ + r * WROWB + ch * 16,
                       wsrc + (size_t)mm * 16384 + (size_t)r * 128 + ch * 8);
        }
        CP_COMMIT();
    }

    // ---- stage x (bf16) ----
    #pragma unroll
    for (int j = 0; j < 4; ++j) {
        int i4 = tid + j * 512;                  // float4 idx over 64x128
        int b  = i4 >> 5, dq = (i4 & 31) * 4;
        float4 f = *(const float4*)(x + (size_t)(b0 + b) * CDIM + h * HD + dq);
        __nv_bfloat162 h01 = __floats2bfloat162_rn(f.x, f.y);
        __nv_bfloat162 h23 = __floats2bfloat162_rn(f.z, f.w);
        uint32_t* ph = (uint32_t*)(smem + SM_X + (size_t)(b * XPITCH + dq) * 2);
        ph[0] = bits2(h01); ph[1] = bits2(h23);
    }

    // ---- exact fp32 S0 partials in the cp.async shadow (x rows are L1-hot) ----
    {
        const int b = tid & 63, part = tid >> 6;
        const float* xb = x + (size_t)(b0 + b) * CDIM + h * HD + part * 16;
        const float* wv = g_wvsum + h * 128 + part * 16;
        float S0 = 0.f;
        #pragma unroll
        for (int j = 0; j < 4; ++j) {
            float4 xv = *(const float4*)(xb + j * 4);
            float4 wf = *(const float4*)(wv + j * 4);
            S0 = fmaf(xv.x, wf.x, S0); S0 = fmaf(xv.y, wf.y, S0);
            S0 = fmaf(xv.z, wf.z, S0); S0 = fmaf(xv.w, wf.w, S0);
        }
        ((float*)(smem + SM_S0))[part * 64 + b] = S0;
    }

    const int mg = wid >> 3;              // 0/1: 32-batch half
    const int n0 = (wid & 7) * 16;        // 16 output cols per warp

    // ---- per-lane ldmatrix offsets ----
    const int a_row = (lane & 7) + ((lane & 8) ? 8 : 0);
    const int a_kof = (lane & 16) ? 8 : 0;
    const int b_n   = n0 + (lane & 7) + ((lane & 16) ? 8 : 0);
    const uint32_t b_lane_off = (uint32_t)b_n * WROWB + ((lane & 8) ? 16 : 0);

    CP_WAIT0();
    __syncthreads();

    // ---- fused mma region: m outer (A reloaded per matrix, regs stay low) ----
    #pragma unroll
    for (int m = 0; m < 3; ++m) {
        float acc[2][2][4];
        #pragma unroll
        for (int a = 0; a < 2; ++a)
            #pragma unroll
            for (int b = 0; b < 2; ++b)
                #pragma unroll
                for (int c = 0; c < 4; ++c) acc[a][b][c] = 0.f;

        const uint32_t buf = sbase + SM_WB + m * WBUF_SZ;
        #pragma unroll
        for (int ktl = 0; ktl < 8; ++ktl) {
            const int k0 = ktl * 16;
            uint32_t A[2][4];
            #pragma unroll
            for (int Mt = 0; Mt < 2; ++Mt) {
                const uint32_t aoff =
                    (uint32_t)((mg * 32 + Mt * 16 + a_row) * XPITCH + k0 + a_kof) * 2;
                ldm_x4(A[Mt][0], A[Mt][1], A[Mt][2], A[Mt][3], sbase + SM_X + aoff);
            }
            uint32_t Bf[2][2];
            ldm_x4(Bf[0][0], Bf[0][1], Bf[1][0], Bf[1][1],
                   buf + b_lane_off + (uint32_t)k0 * 2);
            #pragma unroll
            for (int Mt = 0; Mt < 2; ++Mt)
                #pragma unroll
                for (int Nt = 0; Nt < 2; ++Nt)
                    mma_bf16(acc[Mt][Nt], A[Mt][0], A[Mt][1], A[Mt][2], A[Mt][3],
                             Bf[Nt][0], Bf[Nt][1]);
        }

        float* dst = (float*)(smem + SM_QKV) + (size_t)m * NB * QPITCH;
        #pragma unroll
        for (int Mt = 0; Mt < 2; ++Mt) {
            const int r = mg * 32 + Mt * 16 + g;
            #pragma unroll
            for (int Nt = 0; Nt < 2; ++Nt) {
                int c = n0 + Nt * 8 + 2 * tg;
                dst[r * QPITCH + c]            = acc[Mt][Nt][0];
                dst[r * QPITCH + c + 1]        = acc[Mt][Nt][1];
                dst[(r + 8) * QPITCH + c]      = acc[Mt][Nt][2];
                dst[(r + 8) * QPITCH + c + 1]  = acc[Mt][Nt][3];
            }
        }
    }
    __syncthreads();

    // ================= epilogue: degree-4 separable moment softmax =================
    const float* q_s = (const float*)(smem + SM_QKV);
    const float* k_s = q_s + NB * QPITCH;
    const float* v_s = q_s + 2 * NB * QPITCH;
    float* red  = (float*)(smem + SM_RED);
    float* coef = (float*)(smem + SM_COEF);

    {   // Phase A: K1..K4, S1..S4 over 16 e's (float2 loads)
        const int b = tid & 63, part = tid >> 6;   // 8 parts
        float K1=0,K2=0,K3=0,K4=0, S1=0,S2=0,S3=0,S4=0;
        const float* kb = k_s + b * QPITCH + part * 16;
        const float* vb = v_s + b * QPITCH + part * 16;
        #pragma unroll
        for (int i = 0; i < 8; ++i) {
            float2 kk = *(const float2*)(kb + i * 2);
            float2 vv = *(const float2*)(vb + i * 2);
            float t = kk.x; K1 += t; S1 = fmaf(t, vv.x, S1);
            t *= kk.x;      K2 += t; S2 = fmaf(t, vv.x, S2);
            t *= kk.x;      K3 += t; S3 = fmaf(t, vv.x, S3);
            t *= kk.x;      K4 += t; S4 = fmaf(t, vv.x, S4);
            t = kk.y;       K1 += t; S1 = fmaf(t, vv.y, S1);
            t *= kk.y;      K2 += t; S2 = fmaf(t, vv.y, S2);
            t *= kk.y;      K3 += t; S3 = fmaf(t, vv.y, S3);
            t *= kk.y;      K4 += t; S4 = fmaf(t, vv.y, S4);
        }
        float* rr = red + ((size_t)part * 64 + b) * 10;
        rr[0]=K1; rr[1]=K2; rr[2]=K3; rr[3]=K4;
        rr[4]=S1; rr[5]=S2; rr[6]=S3; rr[7]=S4;
    }
    __syncthreads();

    if (tid < 64) {   // Phase B: combine 8 parts (+S0) + fold 1/n!
        float c[8];
        #pragma unroll
        for (int j = 0; j < 8; ++j) c[j] = 0.f;
        float S0 = 0.f;
        #pragma unroll
        for (int p = 0; p < 8; ++p) {
            const float* rr = red + ((size_t)p * 64 + tid) * 10;
            #pragma unroll
            for (int j = 0; j < 8; ++j) c[j] += rr[j];
            S0 += ((const float*)(smem + SM_S0))[p * 64 + tid];
        }
        float* cc = coef + tid * 10;
        cc[0] = c[0];               cc[1] = c[1] * 0.5f;
        cc[2] = c[2] * (1.f/6.f);   cc[3] = c[3] * (1.f/24.f);
        cc[4] = S0;                 cc[5] = c[4];
        cc[6] = c[5] * 0.5f;        cc[7] = c[6] * (1.f/6.f);
        cc[8] = c[7] * (1.f/24.f);
    }
    __syncthreads();

    {   // Phase C: degree-4 Horner, write gmem directly
        const int b = tid & 63, part = tid >> 6;
        const float* cc = coef + b * 10;
        const float a1=cc[0],a2=cc[1],a3=cc[2],a4=cc[3];
        const float g0=cc[4],g1=cc[5],g2=cc[6],g3=cc[7],g4=cc[8];
        const float* qb = q_s + b * QPITCH + part * 16;
        float o[16];
        #pragma unroll
        for (int i = 0; i < 8; ++i) {
            float2 qq = *(const float2*)(qb + i * 2);
            #pragma unroll
            for (int u = 0; u < 2; ++u) {
                float q = u ? qq.y : qq.x;
                float den = fmaf(a4, q, a3);
                den = fmaf(den, q, a2); den = fmaf(den, q, a1);
                den = fmaf(den, q, 128.0f);
                float num = fmaf(g4, q, g3);
                num = fmaf(num, q, g2); num = fmaf(num, q, g1);
                num = fmaf(num, q, g0);
                o[i * 2 + u] = num * rcpf(den);
            }
        }
        float* dst = out + (size_t)(b0 + b) * CDIM + h * HD + part * 16;
        #pragma unroll
        for (int j = 0; j < 4; ++j)
            *(float4*)(dst + j * 4) = make_float4(o[j*4], o[j*4+1], o[j*4+2], o[j*4+3]);
    }
}

extern "C" void kernel_launch(void* const* d_in, const int* in_sizes, int n_in,
                              void* d_out, int out_size) {
    const float* x   = (const float*)d_in[0];
    const float* Wq  = (const float*)d_in[1];
    const float* Wkv = (const float*)d_in[2];
    float* out = (float*)d_out;

    conv_kernel<<<392, 256>>>(Wq, Wkv);

    cudaFuncSetAttribute(satt_kernel, cudaFuncAttributeMaxDynamicSharedMemorySize, SM_TOTAL);
    dim3 grid(BSZ / NB, NHEAD);
    satt_kernel<<<grid, THREADS, SM_TOTAL>>>(x, out);
}

// round 17
// speedup vs baseline: 2.0432x; 1.1555x over previous
#include <cuda_runtime.h>
#include <cuda_bf16.h>
#include <cstdint>

#define NHEAD 8
#define HD 128
#define BSZ 1024
#define CDIM 1024
#define NB 64
#define THREADS 512
#define SCALE 0.08838834764831845f   // HD^-0.5

#define XPITCH 136    // bf16 elems per x row (272B = 17*16B: ldmatrix conflict-free)
#define QPITCH 130    // f32 elems per qkv row (even: float2-aligned)

// ---- smem byte offsets (no W staging) ----
#define SM_X     0                    // 64*136*2 = 17408
#define SM_QKV   17408                // float[3][64][QPITCH] = 99840 -> 117248
#define SM_S0    117248               // float[8][64] = 2048    -> 119296
#define SM_RED   119296               // float[8][64][10] = 20480 -> 139776
#define SM_COEF  139776               // float[64][10] = 2560   -> 142336
#define SM_TOTAL 142336

// fragment-ordered W: [h][m][ntile 16][ktile 8][lane 32] as uint2 (b0,b1 regs)
// strides (uint2 units): lane=1, ktile=32, ntile=256, m=4096, h=12288
__device__ uint2 g_wfrag[NHEAD * 3 * 16 * 8 * 32];
__device__ float g_wvsum[NHEAD * HD];   // per-head column sums of Wv

__device__ __forceinline__ float rcpf(float x) {
    float y; asm("rcp.approx.ftz.f32 %0, %1;" : "=f"(y) : "f"(x)); return y;
}
__device__ __forceinline__ uint32_t smem_u32(const void* p) {
    uint32_t a;
    asm("{ .reg .u64 t; cvta.to.shared.u64 t, %1; cvt.u32.u64 %0, t; }" : "=r"(a) : "l"(p));
    return a;
}
__device__ __forceinline__ void ldm_x4(uint32_t& r0, uint32_t& r1, uint32_t& r2, uint32_t& r3,
                                       uint32_t addr) {
    asm volatile("ldmatrix.sync.aligned.m8n8.x4.shared.b16 {%0,%1,%2,%3}, [%4];"
                 : "=r"(r0), "=r"(r1), "=r"(r2), "=r"(r3) : "r"(addr));
}
__device__ __forceinline__ void mma_bf16(float c[4],
    uint32_t a0, uint32_t a1, uint32_t a2, uint32_t a3,
    uint32_t b0, uint32_t b1)
{
    asm volatile(
        "mma.sync.aligned.m16n8k16.row.col.f32.bf16.bf16.f32 "
        "{%0,%1,%2,%3}, {%4,%5,%6,%7}, {%8,%9}, {%0,%1,%2,%3};"
        : "+f"(c[0]), "+f"(c[1]), "+f"(c[2]), "+f"(c[3])
        : "r"(a0), "r"(a1), "r"(a2), "r"(a3), "r"(b0), "r"(b1));
}
__device__ __forceinline__ uint32_t bits2(__nv_bfloat162 v) {
    return *reinterpret_cast<uint32_t*>(&v);
}
__device__ __forceinline__ uint32_t packbf(float a, float b) {
    return bits2(__floats2bfloat162_rn(a, b));
}

// ================= prestage: W -> fragment-ordered bf16 (+ Wv column sums) =================
__global__ __launch_bounds__(256) void conv_kernel(
    const float* __restrict__ Wq, const float* __restrict__ Wkv)
{
    if (blockIdx.x >= 384) {
        __shared__ float ps[2][128];
        const int h = blockIdx.x - 384;
        const int tid = threadIdx.x;
        const int d = tid & 127, part = tid >> 7;
        const float* src = Wkv + (size_t)h * 32768 + 16384 + d + (size_t)part * 64 * 128;
        float s = 0.f;
        #pragma unroll 16
        for (int e = 0; e < 64; ++e) s += src[(size_t)e * 128];
        ps[part][d] = s;
        __syncthreads();
        if (part == 0) g_wvsum[h * 128 + d] = ps[0][d] + ps[1][d];
        return;
    }
    // one thread -> one lane-fragment (uint2)
    int t = blockIdx.x * 256 + threadIdx.x;      // 0..98303
    const int lane = t & 31;
    const int kt   = (t >> 5) & 7;
    const int nt   = (t >> 8) & 15;
    const int hm   = t >> 12;                    // 0..23
    const int h    = hm / 3, m = hm % 3;

    const int n = nt * 8 + (lane >> 2);
    const int k = kt * 16 + 2 * (lane & 3);

    const float* src;
    float scl = 1.0f;
    if (m == 0)      src = Wq  + (size_t)h * 16384;
    else if (m == 1) { src = Wkv + (size_t)h * 32768; scl = SCALE; }
    else             src = Wkv + (size_t)h * 32768 + 16384;
    const float* row = src + (size_t)n * HD;

    uint2 frag;
    frag.x = packbf(row[k] * scl,     row[k + 1] * scl);
    frag.y = packbf(row[k + 8] * scl, row[k + 9] * scl);
    g_wfrag[t] = frag;
}

// ================= main kernel =================
__global__ __launch_bounds__(THREADS, 1) void satt_kernel(
    const float* __restrict__ x,
    float* __restrict__ out)
{
    extern __shared__ char smem[];
    const uint32_t sbase = smem_u32(smem);
    const int tid  = threadIdx.x;
    const int wid  = tid >> 5, lane = tid & 31;
    const int g    = lane >> 2, tg = lane & 3;
    const int h    = blockIdx.y;
    const int b0   = blockIdx.x * NB;

    const int mg = wid >> 3;              // 0/1: 32-batch half
    const int nw = wid & 7;               // N-group
    const int n0 = nw * 16;

    // fragment base for this warp: [h][m][ntile = nw*2 + Nt][ktl][lane]
    const uint2* wf_base = g_wfrag + (size_t)h * 12288 + (size_t)nw * 512 + lane;
    // frag(m, Nt, ktl) = wf_base[(m*128 + Nt*8 + ktl) * 32]

    // ---- issue B loads for matrix 0 (overlaps x staging + barrier) ----
    uint2 Bcur[2][8];
    #pragma unroll
    for (int Nt = 0; Nt < 2; ++Nt)
        #pragma unroll
        for (int ktl = 0; ktl < 8; ++ktl)
            Bcur[Nt][ktl] = __ldg(wf_base + ((size_t)Nt * 8 + ktl) * 32);

    // ---- stage x (bf16) ----
    #pragma unroll
    for (int j = 0; j < 4; ++j) {
        int i4 = tid + j * 512;                  // float4 idx over 64x128
        int b  = i4 >> 5, dq = (i4 & 31) * 4;
        float4 f = *(const float4*)(x + (size_t)(b0 + b) * CDIM + h * HD + dq);
        __nv_bfloat162 h01 = __floats2bfloat162_rn(f.x, f.y);
        __nv_bfloat162 h23 = __floats2bfloat162_rn(f.z, f.w);
        uint32_t* ph = (uint32_t*)(smem + SM_X + (size_t)(b * XPITCH + dq) * 2);
        ph[0] = bits2(h01); ph[1] = bits2(h23);
    }

    // ---- exact fp32 S0 partials (x rows L1-hot from staging) ----
    {
        const int b = tid & 63, part = tid >> 6;
        const float* xb = x + (size_t)(b0 + b) * CDIM + h * HD + part * 16;
        const float* wv = g_wvsum + h * 128 + part * 16;
        float S0 = 0.f;
        #pragma unroll
        for (int j = 0; j < 4; ++j) {
            float4 xv = *(const float4*)(xb + j * 4);
            float4 wfv = *(const float4*)(wv + j * 4);
            S0 = fmaf(xv.x, wfv.x, S0); S0 = fmaf(xv.y, wfv.y, S0);
            S0 = fmaf(xv.z, wfv.z, S0); S0 = fmaf(xv.w, wfv.w, S0);
        }
        ((float*)(smem + SM_S0))[part * 64 + b] = S0;
    }

    // ---- per-lane A ldmatrix offsets ----
    const int a_row = (lane & 7) + ((lane & 8) ? 8 : 0);
    const int a_kof = (lane & 16) ? 8 : 0;

    __syncthreads();

    // ---- mma: m outer, B double-buffered from gmem, A via ldmatrix ----
    #pragma unroll
    for (int m = 0; m < 3; ++m) {
        uint2 Bnext[2][8];
        if (m < 2) {
            #pragma unroll
            for (int Nt = 0; Nt < 2; ++Nt)
                #pragma unroll
                for (int ktl = 0; ktl < 8; ++ktl)
                    Bnext[Nt][ktl] =
                        __ldg(wf_base + ((size_t)(m + 1) * 128 + Nt * 8 + ktl) * 32);
        }

        float acc[2][2][4];
        #pragma unroll
        for (int a = 0; a < 2; ++a)
            #pragma unroll
            for (int b = 0; b < 2; ++b)
                #pragma unroll
                for (int c = 0; c < 4; ++c) acc[a][b][c] = 0.f;

        #pragma unroll
        for (int ktl = 0; ktl < 8; ++ktl) {
            const int k0 = ktl * 16;
            uint32_t A[2][4];
            #pragma unroll
            for (int Mt = 0; Mt < 2; ++Mt) {
                const uint32_t aoff =
                    (uint32_t)((mg * 32 + Mt * 16 + a_row) * XPITCH + k0 + a_kof) * 2;
                ldm_x4(A[Mt][0], A[Mt][1], A[Mt][2], A[Mt][3], sbase + SM_X + aoff);
            }
            #pragma unroll
            for (int Mt = 0; Mt < 2; ++Mt)
                #pragma unroll
                for (int Nt = 0; Nt < 2; ++Nt)
                    mma_bf16(acc[Mt][Nt], A[Mt][0], A[Mt][1], A[Mt][2], A[Mt][3],
                             Bcur[Nt][ktl].x, Bcur[Nt][ktl].y);
        }

        float* dst = (float*)(smem + SM_QKV) + (size_t)m * NB * QPITCH;
        #pragma unroll
        for (int Mt = 0; Mt < 2; ++Mt) {
            const int r = mg * 32 + Mt * 16 + g;
            #pragma unroll
            for (int Nt = 0; Nt < 2; ++Nt) {
                int c = n0 + Nt * 8 + 2 * tg;
                dst[r * QPITCH + c]            = acc[Mt][Nt][0];
                dst[r * QPITCH + c + 1]        = acc[Mt][Nt][1];
                dst[(r + 8) * QPITCH + c]      = acc[Mt][Nt][2];
                dst[(r + 8) * QPITCH + c + 1]  = acc[Mt][Nt][3];
            }
        }

        if (m < 2) {
            #pragma unroll
            for (int Nt = 0; Nt < 2; ++Nt)
                #pragma unroll
                for (int ktl = 0; ktl < 8; ++ktl)
                    Bcur[Nt][ktl] = Bnext[Nt][ktl];
        }
    }
    __syncthreads();

    // ================= epilogue: degree-4 separable moment softmax =================
    const float* q_s = (const float*)(smem + SM_QKV);
    const float* k_s = q_s + NB * QPITCH;
    const float* v_s = q_s + 2 * NB * QPITCH;
    float* red  = (float*)(smem + SM_RED);
    float* coef = (float*)(smem + SM_COEF);

    {   // Phase A: K1..K4, S1..S4 over 16 e's (float2 loads)
        const int b = tid & 63, part = tid >> 6;   // 8 parts
        float K1=0,K2=0,K3=0,K4=0, S1=0,S2=0,S3=0,S4=0;
        const float* kb = k_s + b * QPITCH + part * 16;
        const float* vb = v_s + b * QPITCH + part * 16;
        #pragma unroll
        for (int i = 0; i < 8; ++i) {
            float2 kk = *(const float2*)(kb + i * 2);
            float2 vv = *(const float2*)(vb + i * 2);
            float t = kk.x; K1 += t; S1 = fmaf(t, vv.x, S1);
            t *= kk.x;      K2 += t; S2 = fmaf(t, vv.x, S2);
            t *= kk.x;      K3 += t; S3 = fmaf(t, vv.x, S3);
            t *= kk.x;      K4 += t; S4 = fmaf(t, vv.x, S4);
            t = kk.y;       K1 += t; S1 = fmaf(t, vv.y, S1);
            t *= kk.y;      K2 += t; S2 = fmaf(t, vv.y, S2);
            t *= kk.y;      K3 += t; S3 = fmaf(t, vv.y, S3);
            t *= kk.y;      K4 += t; S4 = fmaf(t, vv.y, S4);
        }
        float* rr = red + ((size_t)part * 64 + b) * 10;
        rr[0]=K1; rr[1]=K2; rr[2]=K3; rr[3]=K4;
        rr[4]=S1; rr[5]=S2; rr[6]=S3; rr[7]=S4;
    }
    __syncthreads();

    if (tid < 64) {   // Phase B: combine 8 parts (+S0) + fold 1/n!
        float c[8];
        #pragma unroll
        for (int j = 0; j < 8; ++j) c[j] = 0.f;
        float S0 = 0.f;
        #pragma unroll
        for (int p = 0; p < 8; ++p) {
            const float* rr = red + ((size_t)p * 64 + tid) * 10;
            #pragma unroll
            for (int j = 0; j < 8; ++j) c[j] += rr[j];
            S0 += ((const float*)(smem + SM_S0))[p * 64 + tid];
        }
        float* cc = coef + tid * 10;
        cc[0] = c[0];               cc[1] = c[1] * 0.5f;
        cc[2] = c[2] * (1.f/6.f);   cc[3] = c[3] * (1.f/24.f);
        cc[4] = S0;                 cc[5] = c[4];
        cc[6] = c[5] * 0.5f;        cc[7] = c[6] * (1.f/6.f);
        cc[8] = c[7] * (1.f/24.f);
    }
    __syncthreads();

    {   // Phase C: degree-4 Horner, write gmem directly
        const int b = tid & 63, part = tid >> 6;
        const float* cc = coef + b * 10;
        const float a1=cc[0],a2=cc[1],a3=cc[2],a4=cc[3];
        const float g0=cc[4],g1=cc[5],g2=cc[6],g3=cc[7],g4=cc[8];
        const float* qb = q_s + b * QPITCH + part * 16;
        float o[16];
        #pragma unroll
        for (int i = 0; i < 8; ++i) {
            float2 qq = *(const float2*)(qb + i * 2);
            #pragma unroll
            for (int u = 0; u < 2; ++u) {
                float q = u ? qq.y : qq.x;
                float den = fmaf(a4, q, a3);
                den = fmaf(den, q, a2); den = fmaf(den, q, a1);
                den = fmaf(den, q, 128.0f);
                float num = fmaf(g4, q, g3);
                num = fmaf(num, q, g2); num = fmaf(num, q, g1);
                num = fmaf(num, q, g0);
                o[i * 2 + u] = num * rcpf(den);
            }
        }
        float* dst = out + (size_t)(b0 + b) * CDIM + h * HD + part * 16;
        #pragma unroll
        for (int j = 0; j < 4; ++j)
            *(float4*)(dst + j * 4) = make_float4(o[j*4], o[j*4+1], o[j*4+2], o[j*4+3]);
    }
}

extern "C" void kernel_launch(void* const* d_in, const int* in_sizes, int n_in,
                              void* d_out, int out_size) {
    const float* x   = (const float*)d_in[0];
    const float* Wq  = (const float*)d_in[1];
    const float* Wkv = (const float*)d_in[2];
    float* out = (float*)d_out;

    conv_kernel<<<392, 256>>>(Wq, Wkv);

    cudaFuncSetAttribute(satt_kernel, cudaFuncAttributeMaxDynamicSharedMemorySize, SM_TOTAL);
    dim3 grid(BSZ / NB, NHEAD);
    satt_kernel<<<grid, THREADS, SM_TOTAL>>>(x, out);
}